// round 11
// baseline (speedup 1.0000x reference)
#include <cuda_runtime.h>
#include <cuda_fp16.h>
#include <cstdint>
#include <cstddef>

#define BB 128
#define TT 128
#define HH 1024
#define H3 3072
#define NBY 128    // CTAs per by-group barrier (128 o-tiles)

// Scratch (static device globals -- no dynamic allocation allowed).
__device__ float   g_xp[50331648ULL];           // [T][B][3H] fp32
__device__ __half  g_whh[2ULL * 3 * HH * HH];   // Wh fp16
__device__ __half  g_wxh[2ULL * 3 * HH * HH];   // Wx fp16
__device__ __half  g_x16[(size_t)BB * TT * HH]; // input fp16
__device__ __half  g_y16[(size_t)BB * TT * HH]; // layer-1 output fp16
__device__ uint8_t g_himg[2][2][131072];        // h images: [parity][by][4 K-quarters x 32KB]
__device__ float   g_bias[2 * H3];              // xproj bias: bx+bh (r,z), bx (n)
__device__ unsigned g_bc[2];                    // per-by barrier
__device__ unsigned g_bp[2];

__device__ __forceinline__ uint32_t pack_h2(float x, float y) {
    __half2 h = __floats2half2_rn(x, y);
    return *reinterpret_cast<uint32_t*>(&h);
}

__device__ __forceinline__ void mma_f16(float d[4], const uint32_t a[4], const uint32_t b[2]) {
    asm volatile(
        "mma.sync.aligned.m16n8k16.row.col.f32.f16.f16.f32 "
        "{%0,%1,%2,%3}, {%4,%5,%6,%7}, {%8,%9}, {%0,%1,%2,%3};"
        : "+f"(d[0]), "+f"(d[1]), "+f"(d[2]), "+f"(d[3])
        : "r"(a[0]), "r"(a[1]), "r"(a[2]), "r"(a[3]), "r"(b[0]), "r"(b[1]));
}

__device__ __forceinline__ void ldsm4(uint32_t& r0, uint32_t& r1, uint32_t& r2, uint32_t& r3,
                                      uint32_t addr) {
    asm volatile("ldmatrix.sync.aligned.m8n8.x4.shared.b16 {%0,%1,%2,%3}, [%4];"
                 : "=r"(r0), "=r"(r1), "=r"(r2), "=r"(r3) : "r"(addr));
}
__device__ __forceinline__ void ldsm2(uint32_t& r0, uint32_t& r1, uint32_t addr) {
    asm volatile("ldmatrix.sync.aligned.m8n8.x2.shared.b16 {%0,%1}, [%2];"
                 : "=r"(r0), "=r"(r1) : "r"(addr));
}

__device__ __forceinline__ void mbar_wait(uint32_t mbar, uint32_t parity) {
    asm volatile(
        "{\n\t.reg .pred P;\n\t"
        "WL_%=:\n\t"
        "mbarrier.try_wait.parity.acquire.cta.shared::cta.b64 P, [%0], %1, 0x989680;\n\t"
        "@P bra.uni WD_%=;\n\t"
        "bra.uni WL_%=;\n\t"
        "WD_%=:\n\t}"
        :: "r"(mbar), "r"(parity) : "memory");
}

// Per-by-group barrier (128 CTAs each; halves independent).
__device__ __forceinline__ void grid_sync_by(int by) {
    __syncthreads();
    if (threadIdx.x == 0) {
        volatile unsigned* vphs = &g_bp[by];
        unsigned ph = *vphs;
        __threadfence();
        unsigned ticket = atomicAdd(&g_bc[by], 1u);
        if (ticket == NBY - 1) {
            *((volatile unsigned*)&g_bc[by]) = 0u;
            __threadfence();
            *vphs = ph + 1u;
        } else {
            while (*vphs == ph) {}
            __threadfence();
        }
    }
    __syncthreads();
}

// ---------------------------------------------------------------------------
__global__ void cvt_f16_kernel(const float* __restrict__ src, __half* __restrict__ dst, int n4)
{
    int i = blockIdx.x * blockDim.x + threadIdx.x;
    if (i < n4) {
        float4 v = ((const float4*)src)[i];
        ((uint2*)dst)[i] = make_uint2(pack_h2(v.x, v.y), pack_h2(v.z, v.w));
    }
}

// h0 (fp32 [B,H]) -> parity-0 h images (fp16, K-quartered pre-swizzled layout).
__global__ void cvt_img_kernel(const float* __restrict__ src)
{
    int i = blockIdx.x * blockDim.x + threadIdx.x;   // 16384 chunks (16B)
    int b = i >> 7, c = i & 127;                     // c: chunk of 8 units
    int by = b >> 6, row = b & 63;
    const float* s = src + (size_t)b * HH + c * 8;
    float4 v0 = ((const float4*)s)[0];
    float4 v1 = ((const float4*)s)[1];
    uint4 o;
    o.x = pack_h2(v0.x, v0.y); o.y = pack_h2(v0.z, v0.w);
    o.z = pack_h2(v1.x, v1.y); o.w = pack_h2(v1.z, v1.w);
    int q  = c >> 5;          // K-quarter
    int c2 = c & 31;          // chunk within quarter
    uint32_t off = (uint32_t)q * 32768u + (uint32_t)row * 512u
                 + (uint32_t)((c2 ^ (row & 7)) << 4);
    *(uint4*)(&g_himg[0][by][0] + off) = o;
}

// Combined bias for xproj: bx + bh for gates r,z ; bx only for gate n.
__global__ void bias_kernel(const float* __restrict__ bx, const float* __restrict__ bh,
                            float* __restrict__ out)
{
    int i = blockIdx.x * blockDim.x + threadIdx.x;
    if (i < 2 * H3) {
        int n = i % H3;
        float v = bx[i];
        if (n < 2 * HH) v += bh[i];
        out[i] = v;
    }
}

// ---------------------------------------------------------------------------
// xproj v2 (unchanged from R10): all-fp16, cp.async 3-stage pipeline.
// ---------------------------------------------------------------------------
#define XSTG 10240
#define XB0  30720

__global__ __launch_bounds__(256) void xproj2_kernel(
    const __half* __restrict__ A16, const __half* __restrict__ W16,
    const float*  __restrict__ bias, float* __restrict__ xp)
{
    extern __shared__ uint8_t xsm[];
    const uint32_t smb = (uint32_t)__cvta_generic_to_shared(xsm);

    const int tid  = threadIdx.x;
    const int lane = tid & 31;
    const int wid  = tid >> 5;
    const int wm   = (wid >> 2) * 64;
    const int wn   = (wid & 3) * 32;
    const int m0   = blockIdx.y * 128;
    const int n0   = blockIdx.x * 128;

    const __half* gsrc[4]; uint32_t sdst[4];
    #pragma unroll
    for (int j = 0; j < 4; j++) {
        int idx = tid + j * 256;
        if (idx < 512) {
            int row = idx >> 2, kv = idx & 3;
            int m = m0 + row;
            int b = m & (BB - 1);
            int t = m >> 7;
            gsrc[j] = A16 + ((size_t)b * TT + t) * HH + kv * 8;
            sdst[j] = (uint32_t)(row * 80 + kv * 16);
        } else {
            int i2 = idx - 512;
            int row = i2 >> 2, kv = i2 & 3;
            gsrc[j] = W16 + (size_t)(n0 + row) * HH + kv * 8;
            sdst[j] = (uint32_t)(XB0 + row * 80 + kv * 16);
        }
    }

    #pragma unroll
    for (int s = 0; s < 2; s++) {
        #pragma unroll
        for (int j = 0; j < 4; j++)
            asm volatile("cp.async.cg.shared.global [%0], [%1], 16;"
                         :: "r"(smb + (uint32_t)s * XSTG + sdst[j]), "l"(gsrc[j] + s * 32));
        asm volatile("cp.async.commit_group;");
    }

    float acc[4][4][4];
    #pragma unroll
    for (int a = 0; a < 4; a++)
        #pragma unroll
        for (int b = 0; b < 4; b++)
            #pragma unroll
            for (int c = 0; c < 4; c++) acc[a][b][c] = 0.f;

    const int g  = lane >> 3;
    const int r8 = lane & 7;
    const uint32_t aRow = (uint32_t)(((g & 1) * 8 + r8) * 80 + (g >> 1) * 16);
    const uint32_t bRow = (uint32_t)(((g >> 1) * 8 + r8) * 80 + (g & 1) * 16);

    const int NKT = HH / 32;
    for (int kt = 0; kt < NKT; kt++) {
        asm volatile("cp.async.wait_group 1;");
        __syncthreads();

        if (kt + 2 < NKT) {
            uint32_t sb = (uint32_t)((kt + 2) % 3) * XSTG;
            #pragma unroll
            for (int j = 0; j < 4; j++)
                asm volatile("cp.async.cg.shared.global [%0], [%1], 16;"
                             :: "r"(smb + sb + sdst[j]), "l"(gsrc[j] + (kt + 2) * 32));
        }
        asm volatile("cp.async.commit_group;");

        const uint32_t aB = smb + (uint32_t)(kt % 3) * XSTG;
        const uint32_t bB = aB + XB0;
        #pragma unroll
        for (int kk = 0; kk < 2; kk++) {
            uint32_t kb = (uint32_t)kk * 32;
            uint32_t af[4][4], bf[2][4];
            #pragma unroll
            for (int mt = 0; mt < 4; mt++)
                ldsm4(af[mt][0], af[mt][1], af[mt][2], af[mt][3],
                      aB + (uint32_t)(wm + mt * 16) * 80 + aRow + kb);
            #pragma unroll
            for (int nb2 = 0; nb2 < 2; nb2++)
                ldsm4(bf[nb2][0], bf[nb2][1], bf[nb2][2], bf[nb2][3],
                      bB + (uint32_t)(wn + nb2 * 16) * 80 + bRow + kb);
            #pragma unroll
            for (int mt = 0; mt < 4; mt++)
                #pragma unroll
                for (int nb2 = 0; nb2 < 2; nb2++) {
                    mma_f16(acc[mt][nb2 * 2],     af[mt], &bf[nb2][0]);
                    mma_f16(acc[mt][nb2 * 2 + 1], af[mt], &bf[nb2][2]);
                }
        }
    }

    #pragma unroll
    for (int mt = 0; mt < 4; mt++) {
        int r = m0 + wm + mt * 16 + (lane >> 2);
        #pragma unroll
        for (int nt = 0; nt < 4; nt++) {
            int cg = n0 + wn + nt * 8 + (lane & 3) * 2;
            float2 bz = *(const float2*)(bias + cg);
            float2 v0 = make_float2(acc[mt][nt][0] + bz.x, acc[mt][nt][1] + bz.y);
            float2 v1 = make_float2(acc[mt][nt][2] + bz.x, acc[mt][nt][3] + bz.y);
            *(float2*)(xp + (size_t)r * H3 + cg)       = v0;
            *(float2*)(xp + (size_t)(r + 8) * H3 + cg) = v1;
        }
    }
}

// ---------------------------------------------------------------------------
// Persistent recurrence v4: 2 CTAs/SM. CTA = 8 units x 64 batches (24 B-rows),
// Wh 48 KB resident; h streamed as 4 K-quarter phases through 2x32 KB slots.
// Grid (128, 2) = 256 CTAs, all resident; per-by barriers; co-resident CTAs
// from the two independent by-chains hide each other's latencies.
// ---------------------------------------------------------------------------
#define WOFF 1024
#define HOFF (WOFF + 24 * 2048)          // 50176
#define SLOTB 32768
#define SMEM_TOT (HOFF + 2 * SLOTB)      // 115712 (113 KB)

__global__ __launch_bounds__(384, 2) void persist_kernel(
    const __half* __restrict__ Wh_h,     // fp16 [3,H,H] (layer slice)
    const float*  __restrict__ bhn,      // [H] gate-n hidden bias
    const float*  __restrict__ h0l,      // fp32 [B,H] initial hidden
    const float*  __restrict__ xp,       // [T,B,3H]
    float*        __restrict__ y,        // [B,T,H]
    __half*       __restrict__ y16,      // [B,T,H] fp16
    float*        __restrict__ hlast)    // fp32 [B,H]
{
    extern __shared__ uint8_t dsm[];
    const uint32_t smbase = (uint32_t)__cvta_generic_to_shared(dsm);
    const int tid  = threadIdx.x;
    const int lane = tid & 31;
    const int wid  = tid >> 5;           // 0..11
    const int o0   = blockIdx.x * 8;     // unit base
    const int by   = blockIdx.y;
    const int b0   = by * 64;
    const int wm   = (wid / 3) * 16;     // 0,16,32,48
    const int wn   = (wid % 3) * 8;      // 0,8,16

    // Header: bh_n (8 floats) + two mbarriers at +64, +72.
    if (tid < 8) ((float*)dsm)[tid] = bhn[o0 + tid];
    if (tid == 0) {
        asm volatile("mbarrier.init.shared.b64 [%0], %1;" :: "r"(smbase + 64), "r"(1u) : "memory");
        asm volatile("mbarrier.init.shared.b64 [%0], %1;" :: "r"(smbase + 72), "r"(1u) : "memory");
    }

    // One-time Wh load: 24 rows (r = 3*u+g) x 128 chunks(16B) = 3072 chunks.
    for (int i = tid; i < 3072; i += 384) {
        int r = i >> 7, c = i & 127;
        int u = r / 3, g = r - 3 * u;
        const __half* src = Wh_h + ((size_t)(g * HH + o0 + u)) * HH + c * 8;
        uint32_t dst = smbase + WOFF + (uint32_t)r * 2048 + (uint32_t)((c ^ (r & 7)) << 4);
        asm volatile("cp.async.cg.shared.global [%0], [%1], 16;" :: "r"(dst), "l"(src));
    }
    asm volatile("cp.async.commit_group;");

    // Epilogue mapping: 256 threads -> (batch eb, 2 units eu0).
    const int eb  = tid >> 2;            // 0..63
    const int eu0 = (tid & 3) * 2;       // 0,2,4,6
    const int ebg = b0 + eb;
    const int og  = o0 + eu0;
    const uint32_t eq  = (uint32_t)(og >> 8);
    const uint32_t ec2 = (uint32_t)((og >> 3) & 31);
    const uint32_t eoff = eq * 32768u + (uint32_t)eb * 512u
                        + ((ec2 ^ (uint32_t)(eb & 7)) << 4) + (uint32_t)(og & 7) * 2u;

    // h carried in registers (2 units).
    float hv0 = 0.f, hv1 = 0.f;
    if (tid < 256) {
        float2 h02 = *(const float2*)(h0l + (size_t)ebg * HH + og);
        hv0 = h02.x; hv1 = h02.y;
    }

    asm volatile("cp.async.wait_group 0;");
    __syncthreads();

    // ldsm lane constants.
    const int g  = lane >> 3;
    const int r8 = lane & 7;
    const int arow = wm + (g & 1) * 8 + r8;       // batch row in slot
    const uint32_t aBase = (uint32_t)arow * 512u;
    const uint32_t arm = (uint32_t)(arow & 7);
    const uint32_t ag  = (uint32_t)(g >> 1);
    const int l2  = lane & 15;
    const int brr = wn + (l2 & 7);                // Wh row
    const uint32_t bBase = smbase + WOFF + (uint32_t)brr * 2048u;
    const uint32_t brm = (uint32_t)(brr & 7);
    const uint32_t bg2 = (uint32_t)(l2 >> 3);

    const uint32_t s0 = smbase + HOFF;
    const uint32_t s1 = smbase + HOFF + SLOTB;
    uint32_t p0 = 0, p1 = 0;

    for (int t = 0; t < TT; t++) {
        const uint8_t* img = &g_himg[t & 1][by][0];

        // Issue quarters 0,1 into slots 0,1.
        if (tid == 0) {
            asm volatile("mbarrier.arrive.expect_tx.shared.b64 _, [%0], %1;"
                         :: "r"(smbase + 64), "r"((uint32_t)SLOTB) : "memory");
            asm volatile("cp.async.bulk.shared::cta.global.mbarrier::complete_tx::bytes "
                         "[%0], [%1], %2, [%3];"
                         :: "r"(s0), "l"(img), "r"((uint32_t)SLOTB), "r"(smbase + 64) : "memory");
            asm volatile("mbarrier.arrive.expect_tx.shared.b64 _, [%0], %1;"
                         :: "r"(smbase + 72), "r"((uint32_t)SLOTB) : "memory");
            asm volatile("cp.async.bulk.shared::cta.global.mbarrier::complete_tx::bytes "
                         "[%0], [%1], %2, [%3];"
                         :: "r"(s1), "l"(img + SLOTB), "r"((uint32_t)SLOTB), "r"(smbase + 72) : "memory");
        }

        // Prefetch xp (hidden under GEMM).
        float2 xr2, xz2, xn2;
        if (tid < 256) {
            const float* xpr = xp + (size_t)t * BB * H3 + (size_t)ebg * H3 + og;
            xr2 = *(const float2*)(xpr);
            xz2 = *(const float2*)(xpr + HH);
            xn2 = *(const float2*)(xpr + 2 * HH);
        }

        float acc[4];
        acc[0] = acc[1] = acc[2] = acc[3] = 0.f;

        // Phase 0: quarter 0 (slot0), kt 0..15.
        mbar_wait(smbase + 64, p0); p0 ^= 1;
        #pragma unroll
        for (int kk = 0; kk < 16; kk++) {
            uint32_t af[4], bf[2];
            ldsm4(af[0], af[1], af[2], af[3],
                  s0 + aBase + (((2u * kk + ag) ^ arm) << 4));
            ldsm2(bf[0], bf[1], bBase + (((2u * (uint32_t)kk + bg2) ^ brm) << 4));
            mma_f16(acc, af, bf);
        }
        __syncthreads();  // slot0 reads done
        if (tid == 0) {
            asm volatile("mbarrier.arrive.expect_tx.shared.b64 _, [%0], %1;"
                         :: "r"(smbase + 64), "r"((uint32_t)SLOTB) : "memory");
            asm volatile("cp.async.bulk.shared::cta.global.mbarrier::complete_tx::bytes "
                         "[%0], [%1], %2, [%3];"
                         :: "r"(s0), "l"(img + 2 * SLOTB), "r"((uint32_t)SLOTB), "r"(smbase + 64) : "memory");
        }

        // Phase 1: quarter 1 (slot1), kt 16..31.
        mbar_wait(smbase + 72, p1); p1 ^= 1;
        #pragma unroll
        for (int kk = 0; kk < 16; kk++) {
            uint32_t kt = 16u + (uint32_t)kk;
            uint32_t af[4], bf[2];
            ldsm4(af[0], af[1], af[2], af[3],
                  s1 + aBase + (((2u * kk + ag) ^ arm) << 4));
            ldsm2(bf[0], bf[1], bBase + (((2u * kt + bg2) ^ brm) << 4));
            mma_f16(acc, af, bf);
        }
        __syncthreads();  // slot1 reads done
        if (tid == 0) {
            asm volatile("mbarrier.arrive.expect_tx.shared.b64 _, [%0], %1;"
                         :: "r"(smbase + 72), "r"((uint32_t)SLOTB) : "memory");
            asm volatile("cp.async.bulk.shared::cta.global.mbarrier::complete_tx::bytes "
                         "[%0], [%1], %2, [%3];"
                         :: "r"(s1), "l"(img + 3 * SLOTB), "r"((uint32_t)SLOTB), "r"(smbase + 72) : "memory");
        }

        // Phase 2: quarter 2 (slot0), kt 32..47.
        mbar_wait(smbase + 64, p0); p0 ^= 1;
        #pragma unroll
        for (int kk = 0; kk < 16; kk++) {
            uint32_t kt = 32u + (uint32_t)kk;
            uint32_t af[4], bf[2];
            ldsm4(af[0], af[1], af[2], af[3],
                  s0 + aBase + (((2u * kk + ag) ^ arm) << 4));
            ldsm2(bf[0], bf[1], bBase + (((2u * kt + bg2) ^ brm) << 4));
            mma_f16(acc, af, bf);
        }

        // Phase 3: quarter 3 (slot1), kt 48..63.
        mbar_wait(smbase + 72, p1); p1 ^= 1;
        #pragma unroll
        for (int kk = 0; kk < 16; kk++) {
            uint32_t kt = 48u + (uint32_t)kk;
            uint32_t af[4], bf[2];
            ldsm4(af[0], af[1], af[2], af[3],
                  s1 + aBase + (((2u * kk + ag) ^ arm) << 4));
            ldsm2(bf[0], bf[1], bBase + (((2u * kt + bg2) ^ brm) << 4));
            mma_f16(acc, af, bf);
        }
        __syncthreads();  // all slot reads done -> Cs alias safe

        // Scatter accumulators: Cs[64][28] fp32 aliased onto slot region.
        float* Cs = (float*)(dsm + HOFF);
        {
            int r = wm + (lane >> 2);
            int c = wn + (lane & 3) * 2;
            Cs[r * 28 + c]           = acc[0];
            Cs[r * 28 + c + 1]       = acc[1];
            Cs[(r + 8) * 28 + c]     = acc[2];
            Cs[(r + 8) * 28 + c + 1] = acc[3];
        }
        __syncthreads();

        // Gate fusion: 2 units per thread.
        if (tid < 256) {
            const float* bhn_s = (const float*)dsm;
            float hvn[2];
            float hvp[2] = {hv0, hv1};
            #pragma unroll
            for (int j = 0; j < 2; j++) {
                int ul = eu0 + j;
                float hr = Cs[eb * 28 + 3 * ul + 0];
                float hz = Cs[eb * 28 + 3 * ul + 1];
                float hn = Cs[eb * 28 + 3 * ul + 2] + bhn_s[ul];
                float xr = j ? xr2.y : xr2.x;
                float xz = j ? xz2.y : xz2.x;
                float xn = j ? xn2.y : xn2.x;
                float r  = 1.f / (1.f + __expf(-(xr + hr)));
                float z  = 1.f / (1.f + __expf(-(xz + hz)));
                float n  = tanhf(xn + r * hn);
                hvn[j] = (1.f - z) * n + z * hvp[j];
            }
            hv0 = hvn[0]; hv1 = hvn[1];
            uint32_t hp = pack_h2(hv0, hv1);
            *(float2*)(y + ((size_t)ebg * TT + t) * HH + og) = make_float2(hv0, hv1);
            *(uint32_t*)(y16 + ((size_t)ebg * TT + t) * HH + og) = hp;
            *(uint32_t*)(&g_himg[(t + 1) & 1][by][0] + eoff) = hp;
            if (t == TT - 1)
                *(float2*)(hlast + (size_t)ebg * HH + og) = make_float2(hv0, hv1);
        }

        if (t + 1 < TT) grid_sync_by(by);
    }

    __syncthreads();
    if (tid == 0) {
        asm volatile("mbarrier.inval.shared.b64 [%0];" :: "r"(smbase + 64) : "memory");
        asm volatile("mbarrier.inval.shared.b64 [%0];" :: "r"(smbase + 72) : "memory");
    }
}

// ---------------------------------------------------------------------------
extern "C" void kernel_launch(void* const* d_in, const int* in_sizes, int n_in,
                              void* d_out, int out_size)
{
    (void)in_sizes; (void)n_in; (void)out_size;
    const float* x   = (const float*)d_in[0];
    const float* h0  = (const float*)d_in[1];
    const float* Wx  = (const float*)d_in[2];
    const float* Wh  = (const float*)d_in[3];
    const float* bx  = (const float*)d_in[4];
    const float* bh  = (const float*)d_in[5];
    float* out   = (float*)d_out;              // [B,T,H] then [L,B,H]
    float* hlast = out + (size_t)BB * TT * HH;

    float*  xp  = nullptr;
    __half* whh = nullptr;
    __half* wxh = nullptr;
    __half* x16 = nullptr;
    __half* y16 = nullptr;
    float*  gb  = nullptr;
    cudaGetSymbolAddress((void**)&xp,  g_xp);
    cudaGetSymbolAddress((void**)&whh, g_whh);
    cudaGetSymbolAddress((void**)&wxh, g_wxh);
    cudaGetSymbolAddress((void**)&x16, g_x16);
    cudaGetSymbolAddress((void**)&y16, g_y16);
    cudaGetSymbolAddress((void**)&gb,  g_bias);

    cudaFuncSetAttribute(persist_kernel,
                         cudaFuncAttributeMaxDynamicSharedMemorySize, SMEM_TOT);
    cudaFuncSetAttribute(xproj2_kernel,
                         cudaFuncAttributeMaxDynamicSharedMemorySize, 61440);

    {
        int nw = 2 * 3 * HH * HH / 4;
        cvt_f16_kernel<<<nw / 256, 256>>>(Wh, whh, nw);
        cvt_f16_kernel<<<nw / 256, 256>>>(Wx, wxh, nw);
        int nx = BB * TT * HH / 4;
        cvt_f16_kernel<<<nx / 256, 256>>>(x, x16, nx);
        bias_kernel<<<(2 * H3 + 255) / 256, 256>>>(bx, bh, gb);
    }

    dim3 xgrid(H3 / 128, (BB * TT) / 128);  // (24, 128)
    dim3 pgrid(128, 2);                     // 256 CTAs, 2/SM

    for (int l = 0; l < 2; l++) {
        const __half* A16 = (l == 0) ? x16 : y16;
        xproj2_kernel<<<xgrid, 256, 61440>>>(A16, wxh + (size_t)l * 3 * HH * HH,
                                             gb + (size_t)l * H3, xp);
        cvt_img_kernel<<<64, 256>>>(h0 + (size_t)l * BB * HH);
        persist_kernel<<<pgrid, 384, SMEM_TOT>>>(
            whh + (size_t)l * 3 * HH * HH,
            bh + (size_t)l * H3 + 2 * HH,
            h0 + (size_t)l * BB * HH,
            xp, out, y16,
            hlast + (size_t)l * BB * HH);
    }
}

// round 12
// speedup vs baseline: 1.4123x; 1.4123x over previous
#include <cuda_runtime.h>
#include <cuda_fp16.h>
#include <cstdint>
#include <cstddef>

#define BB 128
#define TT 128
#define HH 1024
#define H3 3072
#define NBY 64     // CTAs per by-group barrier

// Scratch (static device globals -- no dynamic allocation allowed).
__device__ float   g_xp[50331648ULL];           // [T][B][3H] fp32
__device__ __half  g_whh[2ULL * 3 * HH * HH];   // Wh fp16
__device__ __half  g_wxh[2ULL * 3 * HH * HH];   // Wx fp16
__device__ __half  g_x16[(size_t)BB * TT * HH]; // input fp16
__device__ __half  g_y16[(size_t)BB * TT * HH]; // layer-1 output fp16
__device__ uint8_t g_himg[2][262144];           // h images: [parity][by(2) x 128KB]
__device__ float   g_bias[2 * H3];              // xproj bias: bx+bh (r,z), bx (n)
__device__ unsigned g_bc[2];                    // per-by barrier
__device__ unsigned g_bp[2];

__device__ __forceinline__ uint32_t pack_h2(float x, float y) {
    __half2 h = __floats2half2_rn(x, y);
    return *reinterpret_cast<uint32_t*>(&h);
}

__device__ __forceinline__ void mma_f16(float d[4], const uint32_t a[4], const uint32_t b[2]) {
    asm volatile(
        "mma.sync.aligned.m16n8k16.row.col.f32.f16.f16.f32 "
        "{%0,%1,%2,%3}, {%4,%5,%6,%7}, {%8,%9}, {%0,%1,%2,%3};"
        : "+f"(d[0]), "+f"(d[1]), "+f"(d[2]), "+f"(d[3])
        : "r"(a[0]), "r"(a[1]), "r"(a[2]), "r"(a[3]), "r"(b[0]), "r"(b[1]));
}

__device__ __forceinline__ void ldsm4(uint32_t& r0, uint32_t& r1, uint32_t& r2, uint32_t& r3,
                                      uint32_t addr) {
    asm volatile("ldmatrix.sync.aligned.m8n8.x4.shared.b16 {%0,%1,%2,%3}, [%4];"
                 : "=r"(r0), "=r"(r1), "=r"(r2), "=r"(r3) : "r"(addr));
}
__device__ __forceinline__ void ldsm2(uint32_t& r0, uint32_t& r1, uint32_t addr) {
    asm volatile("ldmatrix.sync.aligned.m8n8.x2.shared.b16 {%0,%1}, [%2];"
                 : "=r"(r0), "=r"(r1) : "r"(addr));
}

__device__ __forceinline__ void mbar_wait(uint32_t mbar, uint32_t parity) {
    asm volatile(
        "{\n\t.reg .pred P;\n\t"
        "WL_%=:\n\t"
        "mbarrier.try_wait.parity.acquire.cta.shared::cta.b64 P, [%0], %1, 0x989680;\n\t"
        "@P bra.uni WD_%=;\n\t"
        "bra.uni WL_%=;\n\t"
        "WD_%=:\n\t}"
        :: "r"(mbar), "r"(parity) : "memory");
}

// Per-by-group barrier: 64 CTAs (batch halves are independent).
__device__ __forceinline__ void grid_sync_by(int by) {
    __syncthreads();
    if (threadIdx.x == 0) {
        volatile unsigned* vphs = &g_bp[by];
        unsigned ph = *vphs;
        __threadfence();
        unsigned ticket = atomicAdd(&g_bc[by], 1u);
        if (ticket == NBY - 1) {
            *((volatile unsigned*)&g_bc[by]) = 0u;
            __threadfence();
            *vphs = ph + 1u;
        } else {
            while (*vphs == ph) {}
            __threadfence();
        }
    }
    __syncthreads();
}

// ---------------------------------------------------------------------------
__global__ void cvt_f16_kernel(const float* __restrict__ src, __half* __restrict__ dst, int n4)
{
    int i = blockIdx.x * blockDim.x + threadIdx.x;
    if (i < n4) {
        float4 v = ((const float4*)src)[i];
        ((uint2*)dst)[i] = make_uint2(pack_h2(v.x, v.y), pack_h2(v.z, v.w));
    }
}

// h0 (fp32 [B,H]) -> parity-0 h image (fp16, pre-swizzled smem layout).
__global__ void cvt_img_kernel(const float* __restrict__ src)
{
    int i = blockIdx.x * blockDim.x + threadIdx.x;   // chunk id, 16384 total
    int b = i >> 7, c = i & 127;
    int by = b >> 6, row = b & 63;
    const float* s = src + (size_t)b * HH + c * 8;
    float4 v0 = ((const float4*)s)[0];
    float4 v1 = ((const float4*)s)[1];
    uint4 o;
    o.x = pack_h2(v0.x, v0.y); o.y = pack_h2(v0.z, v0.w);
    o.z = pack_h2(v1.x, v1.y); o.w = pack_h2(v1.z, v1.w);
    int p = c >> 6, c2 = c & 63;
    uint32_t off = (uint32_t)by * 131072u + (uint32_t)p * 65536u
                 + (uint32_t)row * 1024u + (uint32_t)((c2 ^ (row & 7)) << 4);
    *(uint4*)(&g_himg[0][0] + off) = o;
}

// Combined bias for xproj: bx + bh for gates r,z ; bx only for gate n.
__global__ void bias_kernel(const float* __restrict__ bx, const float* __restrict__ bh,
                            float* __restrict__ out)
{
    int i = blockIdx.x * blockDim.x + threadIdx.x;
    if (i < 2 * H3) {
        int n = i % H3;
        float v = bx[i];
        if (n < 2 * HH) v += bh[i];
        out[i] = v;
    }
}

// ---------------------------------------------------------------------------
// xproj v2 (validated): all-fp16, cp.async 3-stage pipeline.
// ---------------------------------------------------------------------------
#define XSTG 10240
#define XB0  30720

__global__ __launch_bounds__(256) void xproj2_kernel(
    const __half* __restrict__ A16, const __half* __restrict__ W16,
    const float*  __restrict__ bias, float* __restrict__ xp)
{
    extern __shared__ uint8_t xsm[];
    const uint32_t smb = (uint32_t)__cvta_generic_to_shared(xsm);

    const int tid  = threadIdx.x;
    const int lane = tid & 31;
    const int wid  = tid >> 5;
    const int wm   = (wid >> 2) * 64;
    const int wn   = (wid & 3) * 32;
    const int m0   = blockIdx.y * 128;
    const int n0   = blockIdx.x * 128;

    const __half* gsrc[4]; uint32_t sdst[4];
    #pragma unroll
    for (int j = 0; j < 4; j++) {
        int idx = tid + j * 256;
        if (idx < 512) {
            int row = idx >> 2, kv = idx & 3;
            int m = m0 + row;
            int b = m & (BB - 1);
            int t = m >> 7;
            gsrc[j] = A16 + ((size_t)b * TT + t) * HH + kv * 8;
            sdst[j] = (uint32_t)(row * 80 + kv * 16);
        } else {
            int i2 = idx - 512;
            int row = i2 >> 2, kv = i2 & 3;
            gsrc[j] = W16 + (size_t)(n0 + row) * HH + kv * 8;
            sdst[j] = (uint32_t)(XB0 + row * 80 + kv * 16);
        }
    }

    #pragma unroll
    for (int s = 0; s < 2; s++) {
        #pragma unroll
        for (int j = 0; j < 4; j++)
            asm volatile("cp.async.cg.shared.global [%0], [%1], 16;"
                         :: "r"(smb + (uint32_t)s * XSTG + sdst[j]), "l"(gsrc[j] + s * 32));
        asm volatile("cp.async.commit_group;");
    }

    float acc[4][4][4];
    #pragma unroll
    for (int a = 0; a < 4; a++)
        #pragma unroll
        for (int b = 0; b < 4; b++)
            #pragma unroll
            for (int c = 0; c < 4; c++) acc[a][b][c] = 0.f;

    const int g  = lane >> 3;
    const int r8 = lane & 7;
    const uint32_t aRow = (uint32_t)(((g & 1) * 8 + r8) * 80 + (g >> 1) * 16);
    const uint32_t bRow = (uint32_t)(((g >> 1) * 8 + r8) * 80 + (g & 1) * 16);

    const int NKT = HH / 32;
    for (int kt = 0; kt < NKT; kt++) {
        asm volatile("cp.async.wait_group 1;");
        __syncthreads();

        if (kt + 2 < NKT) {
            uint32_t sb = (uint32_t)((kt + 2) % 3) * XSTG;
            #pragma unroll
            for (int j = 0; j < 4; j++)
                asm volatile("cp.async.cg.shared.global [%0], [%1], 16;"
                             :: "r"(smb + sb + sdst[j]), "l"(gsrc[j] + (kt + 2) * 32));
        }
        asm volatile("cp.async.commit_group;");

        const uint32_t aB = smb + (uint32_t)(kt % 3) * XSTG;
        const uint32_t bB = aB + XB0;
        #pragma unroll
        for (int kk = 0; kk < 2; kk++) {
            uint32_t kb = (uint32_t)kk * 32;
            uint32_t af[4][4], bf[2][4];
            #pragma unroll
            for (int mt = 0; mt < 4; mt++)
                ldsm4(af[mt][0], af[mt][1], af[mt][2], af[mt][3],
                      aB + (uint32_t)(wm + mt * 16) * 80 + aRow + kb);
            #pragma unroll
            for (int nb2 = 0; nb2 < 2; nb2++)
                ldsm4(bf[nb2][0], bf[nb2][1], bf[nb2][2], bf[nb2][3],
                      bB + (uint32_t)(wn + nb2 * 16) * 80 + bRow + kb);
            #pragma unroll
            for (int mt = 0; mt < 4; mt++)
                #pragma unroll
                for (int nb2 = 0; nb2 < 2; nb2++) {
                    mma_f16(acc[mt][nb2 * 2],     af[mt], &bf[nb2][0]);
                    mma_f16(acc[mt][nb2 * 2 + 1], af[mt], &bf[nb2][2]);
                }
        }
    }

    #pragma unroll
    for (int mt = 0; mt < 4; mt++) {
        int r = m0 + wm + mt * 16 + (lane >> 2);
        #pragma unroll
        for (int nt = 0; nt < 4; nt++) {
            int cg = n0 + wn + nt * 8 + (lane & 3) * 2;
            float2 bz = *(const float2*)(bias + cg);
            float2 v0 = make_float2(acc[mt][nt][0] + bz.x, acc[mt][nt][1] + bz.y);
            float2 v1 = make_float2(acc[mt][nt][2] + bz.x, acc[mt][nt][3] + bz.y);
            *(float2*)(xp + (size_t)r * H3 + cg)       = v0;
            *(float2*)(xp + (size_t)(r + 8) * H3 + cg) = v1;
        }
    }
}

// ---------------------------------------------------------------------------
// Persistent recurrence v5 (R10 structure + in-register gate fusion).
//   CTA: 64 batches x 16 units. B rows ordered [u8grp(2)][gate(3)][u(8)] so a
//   warp's m16 x n24 tile gives each thread acc[r],acc[z],acc[n] at the SAME
//   (batch, unit) positions -> gate fusion with NO smem round-trip.
//   8 warps (4 m-tiles x 2 unit-groups). Grid (64,2)=128, 1 CTA/SM.
// ---------------------------------------------------------------------------
#define WOFF 1024
#define HOFF (WOFF + 48 * 2048)          // 99328
#define SMEM_TOT (HOFF + 131072)         // 230400

__global__ __launch_bounds__(256) void persist_kernel(
    const __half* __restrict__ Wh_h,     // fp16 [3,H,H] (layer slice)
    const float*  __restrict__ bhn,      // [H] gate-n hidden bias
    const float*  __restrict__ h0l,      // fp32 [B,H] initial hidden
    const float*  __restrict__ xp,       // [T,B,3H]
    float*        __restrict__ y,        // [B,T,H]
    __half*       __restrict__ y16,      // [B,T,H] fp16
    float*        __restrict__ hlast)    // fp32 [B,H]
{
    extern __shared__ uint8_t dsm[];
    const uint32_t smbase = (uint32_t)__cvta_generic_to_shared(dsm);
    const int tid  = threadIdx.x;
    const int lane = tid & 31;
    const int wid  = tid >> 5;           // 0..7
    const int o0   = blockIdx.x * 16;    // unit base
    const int by   = blockIdx.y;
    const int b0   = by * 64;
    const int wm   = (wid >> 1) * 16;    // m-tile: 0,16,32,48
    const int ng   = wid & 1;            // unit-group: units ng*8..+8

    // Header: bh_n (16 floats) + two mbarriers at +64, +72.
    if (tid < 16) ((float*)dsm)[tid] = bhn[o0 + tid];
    if (tid == 0) {
        asm volatile("mbarrier.init.shared.b64 [%0], %1;" :: "r"(smbase + 64), "r"(1u) : "memory");
        asm volatile("mbarrier.init.shared.b64 [%0], %1;" :: "r"(smbase + 72), "r"(1u) : "memory");
    }

    // One-time Wh load: 48 rows x 128 chunks. Smem row r = grp*24 + gate*8 + j
    // maps to Wh row (gate, unit = grp*8 + j).
    for (int i = tid; i < 6144; i += 256) {
        int r = i >> 7, c = i & 127;
        int grp = r / 24, rem = r % 24;
        int gate = rem >> 3, j = rem & 7;
        const __half* src = Wh_h + ((size_t)(gate * HH + o0 + grp * 8 + j)) * HH + c * 8;
        uint32_t dst = smbase + WOFF + (uint32_t)r * 2048 + (uint32_t)((c ^ (r & 7)) << 4);
        asm volatile("cp.async.cg.shared.global [%0], [%1], 16;" :: "r"(dst), "l"(src));
    }
    asm volatile("cp.async.commit_group;");

    // Fragment-aligned epilogue mapping (per thread, from the mma C layout):
    //   rows  = wm + lane/4 and +8  (batches)
    //   cols  = 2*(lane%4), +1 within the 8-unit group -> units og, og+1
    const int eb1 = wm + (lane >> 2);
    const int eb2 = eb1 + 8;
    const int ebg1 = b0 + eb1;
    const int ebg2 = b0 + eb2;
    const int u0  = ng * 8 + (lane & 3) * 2;   // local unit
    const int og  = o0 + u0;                   // global unit
    // Pre-swizzled image offsets (2 halves per row write).
    const uint32_t ecc = (uint32_t)(og >> 3);
    const uint32_t ebase = (ecc >> 6) * 65536u + (((ecc & 63u)) << 4) + (uint32_t)(og & 7) * 2u;
    // per-row: + eb*1024 with chunk-xor (eb&7): xor affects bits [4..6]
    const uint32_t eoff1 = (ecc >> 6) * 65536u + (uint32_t)eb1 * 1024u
                         + (((ecc & 63u) ^ (uint32_t)(eb1 & 7)) << 4) + (uint32_t)(og & 7) * 2u;
    const uint32_t eoff2 = (ecc >> 6) * 65536u + (uint32_t)eb2 * 1024u
                         + (((ecc & 63u) ^ (uint32_t)(eb2 & 7)) << 4) + (uint32_t)(og & 7) * 2u;
    (void)ebase;

    // h carried in registers: hv[row][unit j].
    float hv[2][2];
    {
        float2 a = *(const float2*)(h0l + (size_t)ebg1 * HH + og);
        float2 b = *(const float2*)(h0l + (size_t)ebg2 * HH + og);
        hv[0][0] = a.x; hv[0][1] = a.y;
        hv[1][0] = b.x; hv[1][1] = b.y;
    }

    asm volatile("cp.async.wait_group 0;");
    __syncthreads();

    // ldsm lane constants.
    const int g  = lane >> 3;
    const int r8 = lane & 7;
    const int arow = wm + (g & 1) * 8 + r8;          // batch row
    const uint32_t aBase0 = smbase + HOFF + (uint32_t)arow * 1024;
    const uint32_t arm   = (uint32_t)(arow & 7);
    const uint32_t ahalf = (uint32_t)(g >> 1);
    const int l2  = lane & 15;
    const uint32_t brm   = (uint32_t)(l2 & 7);
    const uint32_t bhalf = (uint32_t)(l2 >> 3);
    uint32_t bBase[3];
    #pragma unroll
    for (int gate = 0; gate < 3; gate++)
        bBase[gate] = smbase + WOFF
                    + (uint32_t)(ng * 24 + gate * 8 + (l2 & 7)) * 2048u;

    const float* bhn_s = (const float*)dsm;

    for (int t = 0; t < TT; t++) {
        // Issue both 64 KB bulk copies of this step's h image.
        if (tid == 0) {
            const uint8_t* src = &g_himg[t & 1][0] + (uint32_t)by * 131072u;
            #pragma unroll
            for (int p = 0; p < 2; p++) {
                uint32_t mb = smbase + 64 + (uint32_t)p * 8;
                asm volatile("mbarrier.arrive.expect_tx.shared.b64 _, [%0], %1;"
                             :: "r"(mb), "r"(65536u) : "memory");
                asm volatile(
                    "cp.async.bulk.shared::cta.global.mbarrier::complete_tx::bytes "
                    "[%0], [%1], %2, [%3];"
                    :: "r"(smbase + HOFF + (uint32_t)p * 65536u),
                       "l"(src + p * 65536), "r"(65536u), "r"(mb) : "memory");
            }
        }

        // Prefetch xp for the epilogue (hidden under the GEMM).
        float2 xg[3][2];
        {
            const float* x1 = xp + (size_t)t * BB * H3 + (size_t)ebg1 * H3 + og;
            const float* x2 = xp + (size_t)t * BB * H3 + (size_t)ebg2 * H3 + og;
            #pragma unroll
            for (int gate = 0; gate < 3; gate++) {
                xg[gate][0] = *(const float2*)(x1 + gate * HH);
                xg[gate][1] = *(const float2*)(x2 + gate * HH);
            }
        }

        float acc[3][4];
        #pragma unroll
        for (int gate = 0; gate < 3; gate++)
            #pragma unroll
            for (int c = 0; c < 4; c++) acc[gate][c] = 0.f;

        // Mainloop: 2 phases x 32 K16. Phase p gated by its mbarrier.
        #pragma unroll 1
        for (int p = 0; p < 2; p++) {
            mbar_wait(smbase + 64 + (uint32_t)p * 8, (uint32_t)(t & 1));
            const uint32_t aB = aBase0 + (uint32_t)p * 65536u;
            #pragma unroll
            for (int kk = 0; kk < 32; kk++) {
                uint32_t q   = 2u * (uint32_t)kk + ahalf;             // h chunk (in phase)
                uint32_t cbk = 2u * (uint32_t)(p * 32 + kk) + bhalf;  // Wh chunk (full K)
                uint32_t af[4];
                ldsm4(af[0], af[1], af[2], af[3], aB + ((q ^ arm) << 4));
                #pragma unroll
                for (int gate = 0; gate < 3; gate++) {
                    uint32_t bf[2];
                    ldsm2(bf[0], bf[1], bBase[gate] + ((cbk ^ brm) << 4));
                    mma_f16(acc[gate], af, bf);
                }
            }
        }

        // In-register gate fusion: rows {eb1, eb2} x units {og, og+1}.
        float nh[2][2];
        #pragma unroll
        for (int r = 0; r < 2; r++) {
            #pragma unroll
            for (int j = 0; j < 2; j++) {
                int ci = r * 2 + j;
                float hr = acc[0][ci];
                float hz = acc[1][ci];
                float hn = acc[2][ci] + bhn_s[u0 + j];
                float xr = j ? xg[0][r].y : xg[0][r].x;
                float xz = j ? xg[1][r].y : xg[1][r].x;
                float xn = j ? xg[2][r].y : xg[2][r].x;
                float rr = 1.f / (1.f + __expf(-(xr + hr)));
                float zz = 1.f / (1.f + __expf(-(xz + hz)));
                float nn = tanhf(xn + rr * hn);
                nh[r][j] = (1.f - zz) * nn + zz * hv[r][j];
            }
        }
        hv[0][0] = nh[0][0]; hv[0][1] = nh[0][1];
        hv[1][0] = nh[1][0]; hv[1][1] = nh[1][1];

        uint32_t hp1 = pack_h2(hv[0][0], hv[0][1]);
        uint32_t hp2 = pack_h2(hv[1][0], hv[1][1]);
        *(float2*)(y + ((size_t)ebg1 * TT + t) * HH + og) = make_float2(hv[0][0], hv[0][1]);
        *(float2*)(y + ((size_t)ebg2 * TT + t) * HH + og) = make_float2(hv[1][0], hv[1][1]);
        *(uint32_t*)(y16 + ((size_t)ebg1 * TT + t) * HH + og) = hp1;
        *(uint32_t*)(y16 + ((size_t)ebg2 * TT + t) * HH + og) = hp2;
        uint8_t* dimg = &g_himg[(t + 1) & 1][0] + (uint32_t)by * 131072u;
        *(uint32_t*)(dimg + eoff1) = hp1;
        *(uint32_t*)(dimg + eoff2) = hp2;
        if (t == TT - 1) {
            *(float2*)(hlast + (size_t)ebg1 * HH + og) = make_float2(hv[0][0], hv[0][1]);
            *(float2*)(hlast + (size_t)ebg2 * HH + og) = make_float2(hv[1][0], hv[1][1]);
        }

        if (t + 1 < TT) grid_sync_by(by);
    }

    __syncthreads();
    if (tid == 0) {
        asm volatile("mbarrier.inval.shared.b64 [%0];" :: "r"(smbase + 64) : "memory");
        asm volatile("mbarrier.inval.shared.b64 [%0];" :: "r"(smbase + 72) : "memory");
    }
}

// ---------------------------------------------------------------------------
extern "C" void kernel_launch(void* const* d_in, const int* in_sizes, int n_in,
                              void* d_out, int out_size)
{
    (void)in_sizes; (void)n_in; (void)out_size;
    const float* x   = (const float*)d_in[0];
    const float* h0  = (const float*)d_in[1];
    const float* Wx  = (const float*)d_in[2];
    const float* Wh  = (const float*)d_in[3];
    const float* bx  = (const float*)d_in[4];
    const float* bh  = (const float*)d_in[5];
    float* out   = (float*)d_out;              // [B,T,H] then [L,B,H]
    float* hlast = out + (size_t)BB * TT * HH;

    float*  xp  = nullptr;
    __half* whh = nullptr;
    __half* wxh = nullptr;
    __half* x16 = nullptr;
    __half* y16 = nullptr;
    float*  gb  = nullptr;
    cudaGetSymbolAddress((void**)&xp,  g_xp);
    cudaGetSymbolAddress((void**)&whh, g_whh);
    cudaGetSymbolAddress((void**)&wxh, g_wxh);
    cudaGetSymbolAddress((void**)&x16, g_x16);
    cudaGetSymbolAddress((void**)&y16, g_y16);
    cudaGetSymbolAddress((void**)&gb,  g_bias);

    cudaFuncSetAttribute(persist_kernel,
                         cudaFuncAttributeMaxDynamicSharedMemorySize, SMEM_TOT);
    cudaFuncSetAttribute(xproj2_kernel,
                         cudaFuncAttributeMaxDynamicSharedMemorySize, 61440);

    {
        int nw = 2 * 3 * HH * HH / 4;
        cvt_f16_kernel<<<nw / 256, 256>>>(Wh, whh, nw);
        cvt_f16_kernel<<<nw / 256, 256>>>(Wx, wxh, nw);
        int nx = BB * TT * HH / 4;
        cvt_f16_kernel<<<nx / 256, 256>>>(x, x16, nx);
        bias_kernel<<<(2 * H3 + 255) / 256, 256>>>(bx, bh, gb);
    }

    dim3 xgrid(H3 / 128, (BB * TT) / 128);  // (24, 128)
    dim3 pgrid(64, 2);                      // 128 CTAs, 1/SM

    for (int l = 0; l < 2; l++) {
        const __half* A16 = (l == 0) ? x16 : y16;
        xproj2_kernel<<<xgrid, 256, 61440>>>(A16, wxh + (size_t)l * 3 * HH * HH,
                                             gb + (size_t)l * H3, xp);
        cvt_img_kernel<<<64, 256>>>(h0 + (size_t)l * BB * HH);
        persist_kernel<<<pgrid, 256, SMEM_TOT>>>(
            whh + (size_t)l * 3 * HH * HH,
            bh + (size_t)l * H3 + 2 * HH,
            h0 + (size_t)l * BB * HH,
            xp, out, y16,
            hlast + (size_t)l * BB * HH);
    }
}

// round 13
// speedup vs baseline: 1.5064x; 1.0666x over previous
#include <cuda_runtime.h>
#include <cuda_fp16.h>
#include <cstdint>
#include <cstddef>

#define BB 128
#define TT 128
#define HH 1024
#define H3 3072

// Scratch (static device globals -- no dynamic allocation allowed).
__device__ float   g_xp[50331648ULL];           // [T][B][3H] fp32
__device__ __half  g_whh[2ULL * 3 * HH * HH];   // Wh fp16
__device__ __half  g_wxh[2ULL * 3 * HH * HH];   // Wx fp16
__device__ __half  g_x16[(size_t)BB * TT * HH]; // input fp16
__device__ __half  g_y16[(size_t)BB * TT * HH]; // layer-1 output fp16
__device__ uint8_t g_himg[2][262144];           // h images: [parity][by(2) x 128KB]
__device__ float   g_bias[2 * H3];              // xproj bias: bx+bh (r,z), bx (n)
__device__ unsigned g_arr[2][2];                // producer arrivals [by][half], monotonic
__device__ unsigned g_rd[2];                    // reader copy-complete [by], monotonic

__device__ __forceinline__ uint32_t pack_h2(float x, float y) {
    __half2 h = __floats2half2_rn(x, y);
    return *reinterpret_cast<uint32_t*>(&h);
}

__device__ __forceinline__ void mma_f16(float d[4], const uint32_t a[4], const uint32_t b[2]) {
    asm volatile(
        "mma.sync.aligned.m16n8k16.row.col.f32.f16.f16.f32 "
        "{%0,%1,%2,%3}, {%4,%5,%6,%7}, {%8,%9}, {%0,%1,%2,%3};"
        : "+f"(d[0]), "+f"(d[1]), "+f"(d[2]), "+f"(d[3])
        : "r"(a[0]), "r"(a[1]), "r"(a[2]), "r"(a[3]), "r"(b[0]), "r"(b[1]));
}

__device__ __forceinline__ void ldsm4(uint32_t& r0, uint32_t& r1, uint32_t& r2, uint32_t& r3,
                                      uint32_t addr) {
    asm volatile("ldmatrix.sync.aligned.m8n8.x4.shared.b16 {%0,%1,%2,%3}, [%4];"
                 : "=r"(r0), "=r"(r1), "=r"(r2), "=r"(r3) : "r"(addr));
}
__device__ __forceinline__ void ldsm2(uint32_t& r0, uint32_t& r1, uint32_t addr) {
    asm volatile("ldmatrix.sync.aligned.m8n8.x2.shared.b16 {%0,%1}, [%2];"
                 : "=r"(r0), "=r"(r1) : "r"(addr));
}

__device__ __forceinline__ void mbar_wait(uint32_t mbar, uint32_t parity) {
    asm volatile(
        "{\n\t.reg .pred P;\n\t"
        "WL_%=:\n\t"
        "mbarrier.try_wait.parity.acquire.cta.shared::cta.b64 P, [%0], %1, 0x989680;\n\t"
        "@P bra.uni WD_%=;\n\t"
        "bra.uni WL_%=;\n\t"
        "WD_%=:\n\t}"
        :: "r"(mbar), "r"(parity) : "memory");
}

// ---------------------------------------------------------------------------
__global__ void reset_sync_kernel()
{
    if (threadIdx.x < 2) {
        g_rd[threadIdx.x] = 0u;
        g_arr[threadIdx.x][0] = 0u;
        g_arr[threadIdx.x][1] = 0u;
    }
}

__global__ void cvt_f16_kernel(const float* __restrict__ src, __half* __restrict__ dst, int n4)
{
    int i = blockIdx.x * blockDim.x + threadIdx.x;
    if (i < n4) {
        float4 v = ((const float4*)src)[i];
        ((uint2*)dst)[i] = make_uint2(pack_h2(v.x, v.y), pack_h2(v.z, v.w));
    }
}

// h0 (fp32 [B,H]) -> parity-0 h image (fp16, pre-swizzled smem layout).
__global__ void cvt_img_kernel(const float* __restrict__ src)
{
    int i = blockIdx.x * blockDim.x + threadIdx.x;   // chunk id, 16384 total
    int b = i >> 7, c = i & 127;
    int by = b >> 6, row = b & 63;
    const float* s = src + (size_t)b * HH + c * 8;
    float4 v0 = ((const float4*)s)[0];
    float4 v1 = ((const float4*)s)[1];
    uint4 o;
    o.x = pack_h2(v0.x, v0.y); o.y = pack_h2(v0.z, v0.w);
    o.z = pack_h2(v1.x, v1.y); o.w = pack_h2(v1.z, v1.w);
    int p = c >> 6, c2 = c & 63;
    uint32_t off = (uint32_t)by * 131072u + (uint32_t)p * 65536u
                 + (uint32_t)row * 1024u + (uint32_t)((c2 ^ (row & 7)) << 4);
    *(uint4*)(&g_himg[0][0] + off) = o;
}

// Combined bias for xproj: bx + bh for gates r,z ; bx only for gate n.
__global__ void bias_kernel(const float* __restrict__ bx, const float* __restrict__ bh,
                            float* __restrict__ out)
{
    int i = blockIdx.x * blockDim.x + threadIdx.x;
    if (i < 2 * H3) {
        int n = i % H3;
        float v = bx[i];
        if (n < 2 * HH) v += bh[i];
        out[i] = v;
    }
}

// ---------------------------------------------------------------------------
// xproj v2 (validated): all-fp16, cp.async 3-stage pipeline.
// ---------------------------------------------------------------------------
#define XSTG 10240
#define XB0  30720

__global__ __launch_bounds__(256) void xproj2_kernel(
    const __half* __restrict__ A16, const __half* __restrict__ W16,
    const float*  __restrict__ bias, float* __restrict__ xp)
{
    extern __shared__ uint8_t xsm[];
    const uint32_t smb = (uint32_t)__cvta_generic_to_shared(xsm);

    const int tid  = threadIdx.x;
    const int lane = tid & 31;
    const int wid  = tid >> 5;
    const int wm   = (wid >> 2) * 64;
    const int wn   = (wid & 3) * 32;
    const int m0   = blockIdx.y * 128;
    const int n0   = blockIdx.x * 128;

    const __half* gsrc[4]; uint32_t sdst[4];
    #pragma unroll
    for (int j = 0; j < 4; j++) {
        int idx = tid + j * 256;
        if (idx < 512) {
            int row = idx >> 2, kv = idx & 3;
            int m = m0 + row;
            int b = m & (BB - 1);
            int t = m >> 7;
            gsrc[j] = A16 + ((size_t)b * TT + t) * HH + kv * 8;
            sdst[j] = (uint32_t)(row * 80 + kv * 16);
        } else {
            int i2 = idx - 512;
            int row = i2 >> 2, kv = i2 & 3;
            gsrc[j] = W16 + (size_t)(n0 + row) * HH + kv * 8;
            sdst[j] = (uint32_t)(XB0 + row * 80 + kv * 16);
        }
    }

    #pragma unroll
    for (int s = 0; s < 2; s++) {
        #pragma unroll
        for (int j = 0; j < 4; j++)
            asm volatile("cp.async.cg.shared.global [%0], [%1], 16;"
                         :: "r"(smb + (uint32_t)s * XSTG + sdst[j]), "l"(gsrc[j] + s * 32));
        asm volatile("cp.async.commit_group;");
    }

    float acc[4][4][4];
    #pragma unroll
    for (int a = 0; a < 4; a++)
        #pragma unroll
        for (int b = 0; b < 4; b++)
            #pragma unroll
            for (int c = 0; c < 4; c++) acc[a][b][c] = 0.f;

    const int g  = lane >> 3;
    const int r8 = lane & 7;
    const uint32_t aRow = (uint32_t)(((g & 1) * 8 + r8) * 80 + (g >> 1) * 16);
    const uint32_t bRow = (uint32_t)(((g >> 1) * 8 + r8) * 80 + (g & 1) * 16);

    const int NKT = HH / 32;
    for (int kt = 0; kt < NKT; kt++) {
        asm volatile("cp.async.wait_group 1;");
        __syncthreads();

        if (kt + 2 < NKT) {
            uint32_t sb = (uint32_t)((kt + 2) % 3) * XSTG;
            #pragma unroll
            for (int j = 0; j < 4; j++)
                asm volatile("cp.async.cg.shared.global [%0], [%1], 16;"
                             :: "r"(smb + sb + sdst[j]), "l"(gsrc[j] + (kt + 2) * 32));
        }
        asm volatile("cp.async.commit_group;");

        const uint32_t aB = smb + (uint32_t)(kt % 3) * XSTG;
        const uint32_t bB = aB + XB0;
        #pragma unroll
        for (int kk = 0; kk < 2; kk++) {
            uint32_t kb = (uint32_t)kk * 32;
            uint32_t af[4][4], bf[2][4];
            #pragma unroll
            for (int mt = 0; mt < 4; mt++)
                ldsm4(af[mt][0], af[mt][1], af[mt][2], af[mt][3],
                      aB + (uint32_t)(wm + mt * 16) * 80 + aRow + kb);
            #pragma unroll
            for (int nb2 = 0; nb2 < 2; nb2++)
                ldsm4(bf[nb2][0], bf[nb2][1], bf[nb2][2], bf[nb2][3],
                      bB + (uint32_t)(wn + nb2 * 16) * 80 + bRow + kb);
            #pragma unroll
            for (int mt = 0; mt < 4; mt++)
                #pragma unroll
                for (int nb2 = 0; nb2 < 2; nb2++) {
                    mma_f16(acc[mt][nb2 * 2],     af[mt], &bf[nb2][0]);
                    mma_f16(acc[mt][nb2 * 2 + 1], af[mt], &bf[nb2][2]);
                }
        }
    }

    #pragma unroll
    for (int mt = 0; mt < 4; mt++) {
        int r = m0 + wm + mt * 16 + (lane >> 2);
        #pragma unroll
        for (int nt = 0; nt < 4; nt++) {
            int cg = n0 + wn + nt * 8 + (lane & 3) * 2;
            float2 bz = *(const float2*)(bias + cg);
            float2 v0 = make_float2(acc[mt][nt][0] + bz.x, acc[mt][nt][1] + bz.y);
            float2 v1 = make_float2(acc[mt][nt][2] + bz.x, acc[mt][nt][3] + bz.y);
            *(float2*)(xp + (size_t)r * H3 + cg)       = v0;
            *(float2*)(xp + (size_t)(r + 8) * H3 + cg) = v1;
        }
    }
}

// ---------------------------------------------------------------------------
// Persistent recurrence v6: dataflow sync (producer arrivals per K-half +
// reader copy-complete counter) replaces the monolithic grid barrier; in-
// register gate fusion; merged r/z ldsm4.
//   CTA: 64 batches x 16 units; B rows [u8grp(2)][gate(3)][u(8)].
//   Grid (64,2)=128, 1 CTA/SM.
// ---------------------------------------------------------------------------
#define WOFF 1024
#define HOFF (WOFF + 48 * 2048)          // 99328
#define SMEM_TOT (HOFF + 131072)         // 230400

__global__ __launch_bounds__(256) void persist_kernel(
    const __half* __restrict__ Wh_h,     // fp16 [3,H,H] (layer slice)
    const float*  __restrict__ bhn,      // [H] gate-n hidden bias
    const float*  __restrict__ h0l,      // fp32 [B,H] initial hidden
    const float*  __restrict__ xp,       // [T,B,3H]
    float*        __restrict__ y,        // [B,T,H]
    __half*       __restrict__ y16,      // [B,T,H] fp16
    float*        __restrict__ hlast)    // fp32 [B,H]
{
    extern __shared__ uint8_t dsm[];
    const uint32_t smbase = (uint32_t)__cvta_generic_to_shared(dsm);
    const int tid  = threadIdx.x;
    const int lane = tid & 31;
    const int wid  = tid >> 5;           // 0..7
    const int o0   = blockIdx.x * 16;    // unit base
    const int by   = blockIdx.y;
    const int b0   = by * 64;
    const int half = (blockIdx.x < 32) ? 0 : 1;   // which K-half this CTA produces
    const int wm   = (wid >> 1) * 16;    // m-tile: 0,16,32,48
    const int ng   = wid & 1;            // unit-group: units ng*8..+8

    // Header: bh_n (16 floats) + two mbarriers at +64, +72.
    if (tid < 16) ((float*)dsm)[tid] = bhn[o0 + tid];
    if (tid == 0) {
        asm volatile("mbarrier.init.shared.b64 [%0], %1;" :: "r"(smbase + 64), "r"(1u) : "memory");
        asm volatile("mbarrier.init.shared.b64 [%0], %1;" :: "r"(smbase + 72), "r"(1u) : "memory");
    }

    // One-time Wh load: 48 rows x 128 chunks. Smem row r = grp*24 + gate*8 + j.
    for (int i = tid; i < 6144; i += 256) {
        int r = i >> 7, c = i & 127;
        int grp = r / 24, rem = r % 24;
        int gate = rem >> 3, j = rem & 7;
        const __half* src = Wh_h + ((size_t)(gate * HH + o0 + grp * 8 + j)) * HH + c * 8;
        uint32_t dst = smbase + WOFF + (uint32_t)r * 2048 + (uint32_t)((c ^ (r & 7)) << 4);
        asm volatile("cp.async.cg.shared.global [%0], [%1], 16;" :: "r"(dst), "l"(src));
    }
    asm volatile("cp.async.commit_group;");

    // Fragment-aligned epilogue mapping.
    const int eb1 = wm + (lane >> 2);
    const int eb2 = eb1 + 8;
    const int ebg1 = b0 + eb1;
    const int ebg2 = b0 + eb2;
    const int u0  = ng * 8 + (lane & 3) * 2;
    const int og  = o0 + u0;
    const uint32_t ecc = (uint32_t)(og >> 3);
    const uint32_t eoff1 = (ecc >> 6) * 65536u + (uint32_t)eb1 * 1024u
                         + (((ecc & 63u) ^ (uint32_t)(eb1 & 7)) << 4) + (uint32_t)(og & 7) * 2u;
    const uint32_t eoff2 = (ecc >> 6) * 65536u + (uint32_t)eb2 * 1024u
                         + (((ecc & 63u) ^ (uint32_t)(eb2 & 7)) << 4) + (uint32_t)(og & 7) * 2u;

    // h carried in registers: hv[row][unit j].
    float hv[2][2];
    {
        float2 a = *(const float2*)(h0l + (size_t)ebg1 * HH + og);
        float2 b = *(const float2*)(h0l + (size_t)ebg2 * HH + og);
        hv[0][0] = a.x; hv[0][1] = a.y;
        hv[1][0] = b.x; hv[1][1] = b.y;
    }

    asm volatile("cp.async.wait_group 0;");
    __syncthreads();

    // ldsm lane constants.
    const int g  = lane >> 3;
    const int r8 = lane & 7;
    const int arow = wm + (g & 1) * 8 + r8;          // batch row (A)
    const uint32_t aBase0 = smbase + HOFF + (uint32_t)arow * 1024;
    const uint32_t arm   = (uint32_t)(arow & 7);
    const uint32_t ahalf = (uint32_t)(g >> 1);
    // B r/z merged ldsm4: rows = ng*24 + (g>>1)*8 + r8 (gate r rows 0-7, z 8-15).
    const int browRZ = ng * 24 + (g >> 1) * 8 + r8;
    const uint32_t bBaseRZ = smbase + WOFF + (uint32_t)browRZ * 2048u;
    const uint32_t brmRZ   = (uint32_t)(browRZ & 7);
    const uint32_t khRZ    = (uint32_t)(g & 1);
    // B gate-n ldsm2: rows ng*24+16+.., lanes 0-15.
    const int l2  = lane & 15;
    const int browN = ng * 24 + 16 + (l2 & 7);
    const uint32_t bBaseN = smbase + WOFF + (uint32_t)browN * 2048u;
    const uint32_t brmN   = (uint32_t)(browN & 7);
    const uint32_t khN    = (uint32_t)(l2 >> 3);

    const float* bhn_s = (const float*)dsm;
    volatile unsigned* varr0 = &g_arr[by][0];
    volatile unsigned* varr1 = &g_arr[by][1];
    volatile unsigned* vrd   = &g_rd[by];

    for (int t = 0; t < TT; t++) {
        __syncthreads();   // all warps' prior smem-slot reads + epilogue done

        // Issue bulk copies, gated per K-half on producer arrivals.
        if (tid == 0) {
            const uint8_t* src = &g_himg[t & 1][0] + (uint32_t)by * 131072u;
            if (t > 0) { while (*varr0 < 32u * (unsigned)t) {} __threadfence(); }
            asm volatile("mbarrier.arrive.expect_tx.shared.b64 _, [%0], %1;"
                         :: "r"(smbase + 64), "r"(65536u) : "memory");
            asm volatile("cp.async.bulk.shared::cta.global.mbarrier::complete_tx::bytes "
                         "[%0], [%1], %2, [%3];"
                         :: "r"(smbase + HOFF), "l"(src), "r"(65536u), "r"(smbase + 64) : "memory");
            if (t > 0) { while (*varr1 < 32u * (unsigned)t) {} __threadfence(); }
            asm volatile("mbarrier.arrive.expect_tx.shared.b64 _, [%0], %1;"
                         :: "r"(smbase + 72), "r"(65536u) : "memory");
            asm volatile("cp.async.bulk.shared::cta.global.mbarrier::complete_tx::bytes "
                         "[%0], [%1], %2, [%3];"
                         :: "r"(smbase + HOFF + 65536u), "l"(src + 65536), "r"(65536u),
                            "r"(smbase + 72) : "memory");
        }

        // Prefetch xp for the epilogue (hidden under the GEMM).
        float2 xg[3][2];
        {
            const float* x1 = xp + (size_t)t * BB * H3 + (size_t)ebg1 * H3 + og;
            const float* x2 = xp + (size_t)t * BB * H3 + (size_t)ebg2 * H3 + og;
            #pragma unroll
            for (int gate = 0; gate < 3; gate++) {
                xg[gate][0] = *(const float2*)(x1 + gate * HH);
                xg[gate][1] = *(const float2*)(x2 + gate * HH);
            }
        }

        float acc[3][4];
        #pragma unroll
        for (int gate = 0; gate < 3; gate++)
            #pragma unroll
            for (int c = 0; c < 4; c++) acc[gate][c] = 0.f;

        // Mainloop: 2 phases x 32 K16.
        #pragma unroll 1
        for (int p = 0; p < 2; p++) {
            mbar_wait(smbase + 64 + (uint32_t)p * 8, (uint32_t)(t & 1));
            // After phase-1 copy landed, signal reads complete (this step's
            // global image reads are done; smem is private from here).
            if (p == 1 && tid == 0 && t + 1 < TT) atomicAdd(&g_rd[by], 1u);
            const uint32_t aB = aBase0 + (uint32_t)p * 65536u;
            #pragma unroll
            for (int kk = 0; kk < 32; kk++) {
                uint32_t q   = 2u * (uint32_t)kk;                // h chunk base (in phase)
                uint32_t cbb = 2u * (uint32_t)(p * 32 + kk);     // Wh chunk base (full K)
                uint32_t af[4], brz[4], bn[2];
                ldsm4(af[0], af[1], af[2], af[3], aB + (((q + ahalf) ^ arm) << 4));
                ldsm4(brz[0], brz[1], brz[2], brz[3], bBaseRZ + (((cbb + khRZ) ^ brmRZ) << 4));
                ldsm2(bn[0], bn[1], bBaseN + (((cbb + khN) ^ brmN) << 4));
                mma_f16(acc[0], af, &brz[0]);
                mma_f16(acc[1], af, &brz[2]);
                mma_f16(acc[2], af, bn);
            }
        }

        // In-register gate fusion.
        float nh[2][2];
        #pragma unroll
        for (int r = 0; r < 2; r++) {
            #pragma unroll
            for (int j = 0; j < 2; j++) {
                int ci = r * 2 + j;
                float hr = acc[0][ci];
                float hz = acc[1][ci];
                float hn = acc[2][ci] + bhn_s[u0 + j];
                float xr = j ? xg[0][r].y : xg[0][r].x;
                float xz = j ? xg[1][r].y : xg[1][r].x;
                float xn = j ? xg[2][r].y : xg[2][r].x;
                float rr = 1.f / (1.f + __expf(-(xr + hr)));
                float zz = 1.f / (1.f + __expf(-(xz + hz)));
                float nn = tanhf(xn + rr * hn);
                nh[r][j] = (1.f - zz) * nn + zz * hv[r][j];
            }
        }
        hv[0][0] = nh[0][0]; hv[0][1] = nh[0][1];
        hv[1][0] = nh[1][0]; hv[1][1] = nh[1][1];

        uint32_t hp1 = pack_h2(hv[0][0], hv[0][1]);
        uint32_t hp2 = pack_h2(hv[1][0], hv[1][1]);
        *(float2*)(y + ((size_t)ebg1 * TT + t) * HH + og) = make_float2(hv[0][0], hv[0][1]);
        *(float2*)(y + ((size_t)ebg2 * TT + t) * HH + og) = make_float2(hv[1][0], hv[1][1]);
        *(uint32_t*)(y16 + ((size_t)ebg1 * TT + t) * HH + og) = hp1;
        *(uint32_t*)(y16 + ((size_t)ebg2 * TT + t) * HH + og) = hp2;
        if (t == TT - 1) {
            *(float2*)(hlast + (size_t)ebg1 * HH + og) = make_float2(hv[0][0], hv[0][1]);
            *(float2*)(hlast + (size_t)ebg2 * HH + og) = make_float2(hv[1][0], hv[1][1]);
        } else {
            // Read-safety: all 64 CTAs must have completed their copies of the
            // buffer we are about to overwrite (parity (t+1)&1, read at t-1).
            while (*vrd < 64u * (unsigned)t) {}
            uint8_t* dimg = &g_himg[(t + 1) & 1][0] + (uint32_t)by * 131072u;
            *(uint32_t*)(dimg + eoff1) = hp1;
            *(uint32_t*)(dimg + eoff2) = hp2;
            __syncthreads();   // all image writes done
            if (tid == 0) {
                __threadfence();
                atomicAdd(&g_arr[by][half], 1u);
            }
        }
    }

    __syncthreads();
    if (tid == 0) {
        asm volatile("mbarrier.inval.shared.b64 [%0];" :: "r"(smbase + 64) : "memory");
        asm volatile("mbarrier.inval.shared.b64 [%0];" :: "r"(smbase + 72) : "memory");
    }
}

// ---------------------------------------------------------------------------
extern "C" void kernel_launch(void* const* d_in, const int* in_sizes, int n_in,
                              void* d_out, int out_size)
{
    (void)in_sizes; (void)n_in; (void)out_size;
    const float* x   = (const float*)d_in[0];
    const float* h0  = (const float*)d_in[1];
    const float* Wx  = (const float*)d_in[2];
    const float* Wh  = (const float*)d_in[3];
    const float* bx  = (const float*)d_in[4];
    const float* bh  = (const float*)d_in[5];
    float* out   = (float*)d_out;              // [B,T,H] then [L,B,H]
    float* hlast = out + (size_t)BB * TT * HH;

    float*  xp  = nullptr;
    __half* whh = nullptr;
    __half* wxh = nullptr;
    __half* x16 = nullptr;
    __half* y16 = nullptr;
    float*  gb  = nullptr;
    cudaGetSymbolAddress((void**)&xp,  g_xp);
    cudaGetSymbolAddress((void**)&whh, g_whh);
    cudaGetSymbolAddress((void**)&wxh, g_wxh);
    cudaGetSymbolAddress((void**)&x16, g_x16);
    cudaGetSymbolAddress((void**)&y16, g_y16);
    cudaGetSymbolAddress((void**)&gb,  g_bias);

    cudaFuncSetAttribute(persist_kernel,
                         cudaFuncAttributeMaxDynamicSharedMemorySize, SMEM_TOT);
    cudaFuncSetAttribute(xproj2_kernel,
                         cudaFuncAttributeMaxDynamicSharedMemorySize, 61440);

    {
        int nw = 2 * 3 * HH * HH / 4;
        cvt_f16_kernel<<<nw / 256, 256>>>(Wh, whh, nw);
        cvt_f16_kernel<<<nw / 256, 256>>>(Wx, wxh, nw);
        int nx = BB * TT * HH / 4;
        cvt_f16_kernel<<<nx / 256, 256>>>(x, x16, nx);
        bias_kernel<<<(2 * H3 + 255) / 256, 256>>>(bx, bh, gb);
    }

    dim3 xgrid(H3 / 128, (BB * TT) / 128);  // (24, 128)
    dim3 pgrid(64, 2);                      // 128 CTAs, 1/SM

    for (int l = 0; l < 2; l++) {
        const __half* A16 = (l == 0) ? x16 : y16;
        xproj2_kernel<<<xgrid, 256, 61440>>>(A16, wxh + (size_t)l * 3 * HH * HH,
                                             gb + (size_t)l * H3, xp);
        cvt_img_kernel<<<64, 256>>>(h0 + (size_t)l * BB * HH);
        reset_sync_kernel<<<1, 32>>>();
        persist_kernel<<<pgrid, 256, SMEM_TOT>>>(
            whh + (size_t)l * 3 * HH * HH,
            bh + (size_t)l * H3 + 2 * HH,
            h0 + (size_t)l * BB * HH,
            xp, out, y16,
            hlast + (size_t)l * BB * HH);
    }
}